// round 4
// baseline (speedup 1.0000x reference)
#include <cuda_runtime.h>
#include <cstdint>

// Problem constants
#define L_DIM   2048
#define N_B     2
#define E_DIM   1024
#define H_N     16
#define D_H     64
#define S_DIM   2048
#define K_SEL   1176              // int(2048 * sigmoid(0.3))
#define T_SEL   (S_DIM - K_SEL)   // 872: 0-based ascending rank of threshold
#define SCS     2052              // score row stride in smem floats (bank-skewed)

// Scratch (static device arrays are allowed; cudaMalloc is not)
__device__ float g_Qp[4096 * 1024];
__device__ float g_Kp[4096 * 1024];
__device__ float g_Vp[4096 * 1024];
__device__ float g_O [4096 * 1024];

// ---------------------------------------------------------------------------
// Helpers
// ---------------------------------------------------------------------------
__device__ __forceinline__ unsigned f2key(float f) {
    unsigned u = __float_as_uint(f);
    return (u & 0x80000000u) ? ~u : (u | 0x80000000u);
}
__device__ __forceinline__ float key2f(unsigned k) {
    unsigned u = (k & 0x80000000u) ? (k ^ 0x80000000u) : ~k;
    return __uint_as_float(u);
}
// Fast e^x for x <= 0 (poly exp2, ~1e-7 rel err). Avoids MUFU bottleneck.
__device__ __forceinline__ float fexp(float x) {
    float y = x * 1.4426950408889634f;
    y = fmaxf(y, -120.0f);
    float fl = floorf(y);
    float f  = y - fl;
    float p  =             1.53533619e-4f;
    p = fmaf(p, f, 1.33988744e-3f);
    p = fmaf(p, f, 9.61843736e-3f);
    p = fmaf(p, f, 5.55033247e-2f);
    p = fmaf(p, f, 2.40226479e-1f);
    p = fmaf(p, f, 6.93147203e-1f);
    p = fmaf(p, f, 1.0f);
    return p * __int_as_float(((int)fl + 127) << 23);
}

// ---------------------------------------------------------------------------
// GEMM: C[4096,1024] = A[4096,1024] @ B^T + bias,  B is [1024,1024] row-major
// (nn.Linear semantics: C[i,j] = sum_e A[i,e] * B[j,e] + bias[j])
// BM=BN=128, BK=16, 256 threads, 8x8 micro-tile, register prefetch of next tile.
// ---------------------------------------------------------------------------
__global__ __launch_bounds__(256, 2)
void gemm_bias_kernel(const float* __restrict__ A, const float* __restrict__ B,
                      const float* __restrict__ bias, float* __restrict__ C)
{
    __shared__ float As[16 * 128];
    __shared__ float Bs[16 * 128];
    const int tid = threadIdx.x;
    const int bm = blockIdx.y, bn = blockIdx.x;
    const int ty = tid >> 4, tx = tid & 15;
    const int rr = tid >> 2, k4 = tid & 3;   // loader coords (per-thread)

    float acc[8][8];
#pragma unroll
    for (int i = 0; i < 8; ++i)
#pragma unroll
        for (int j = 0; j < 8; ++j) acc[i][j] = 0.0f;

    const float* Abase = A + (size_t)(bm * 128 + rr) * 1024 + k4 * 4;
    const float* Bbase = B + (size_t)(bn * 128 + rr) * 1024 + k4 * 4;

    // prefetch regs: rows rr and rr+64 of the 128-row tile
    float4 pa0, pa1, pb0, pb1;
    pa0 = *(const float4*)(Abase);
    pa1 = *(const float4*)(Abase + (size_t)64 * 1024);
    pb0 = *(const float4*)(Bbase);
    pb1 = *(const float4*)(Bbase + (size_t)64 * 1024);

    for (int kt = 0; kt < 64; ++kt) {
        // store prefetched tile to smem (k-major, column = row-in-tile)
        As[(k4 * 4 + 0) * 128 + rr] = pa0.x;
        As[(k4 * 4 + 1) * 128 + rr] = pa0.y;
        As[(k4 * 4 + 2) * 128 + rr] = pa0.z;
        As[(k4 * 4 + 3) * 128 + rr] = pa0.w;
        As[(k4 * 4 + 0) * 128 + rr + 64] = pa1.x;
        As[(k4 * 4 + 1) * 128 + rr + 64] = pa1.y;
        As[(k4 * 4 + 2) * 128 + rr + 64] = pa1.z;
        As[(k4 * 4 + 3) * 128 + rr + 64] = pa1.w;
        Bs[(k4 * 4 + 0) * 128 + rr] = pb0.x;
        Bs[(k4 * 4 + 1) * 128 + rr] = pb0.y;
        Bs[(k4 * 4 + 2) * 128 + rr] = pb0.z;
        Bs[(k4 * 4 + 3) * 128 + rr] = pb0.w;
        Bs[(k4 * 4 + 0) * 128 + rr + 64] = pb1.x;
        Bs[(k4 * 4 + 1) * 128 + rr + 64] = pb1.y;
        Bs[(k4 * 4 + 2) * 128 + rr + 64] = pb1.z;
        Bs[(k4 * 4 + 3) * 128 + rr + 64] = pb1.w;
        __syncthreads();

        if (kt < 63) {    // issue next-tile loads; latency hidden by compute
            const int off = (kt + 1) * 16;
            pa0 = *(const float4*)(Abase + off);
            pa1 = *(const float4*)(Abase + (size_t)64 * 1024 + off);
            pb0 = *(const float4*)(Bbase + off);
            pb1 = *(const float4*)(Bbase + (size_t)64 * 1024 + off);
        }

#pragma unroll
        for (int k = 0; k < 16; ++k) {
            const float4 a0 = *(const float4*)(As + k * 128 + ty * 4);
            const float4 a1 = *(const float4*)(As + k * 128 + 64 + ty * 4);
            const float4 b0 = *(const float4*)(Bs + k * 128 + tx * 4);
            const float4 b1 = *(const float4*)(Bs + k * 128 + 64 + tx * 4);
            const float av[8] = {a0.x, a0.y, a0.z, a0.w, a1.x, a1.y, a1.z, a1.w};
            const float bv[8] = {b0.x, b0.y, b0.z, b0.w, b1.x, b1.y, b1.z, b1.w};
#pragma unroll
            for (int ii = 0; ii < 8; ++ii)
#pragma unroll
                for (int jj = 0; jj < 8; ++jj)
                    acc[ii][jj] = fmaf(av[ii], bv[jj], acc[ii][jj]);
        }
        __syncthreads();
    }
    // Epilogue with bias
#pragma unroll
    for (int jh = 0; jh < 2; ++jh) {
        const int col = bn * 128 + jh * 64 + tx * 4;
        const float4 bb = *(const float4*)(bias + col);
#pragma unroll
        for (int ih = 0; ih < 2; ++ih) {
#pragma unroll
            for (int i = 0; i < 4; ++i) {
                const int row = bm * 128 + ih * 64 + ty * 4 + i;
                float4 o;
                o.x = acc[ih * 4 + i][jh * 4 + 0] + bb.x;
                o.y = acc[ih * 4 + i][jh * 4 + 1] + bb.y;
                o.z = acc[ih * 4 + i][jh * 4 + 2] + bb.z;
                o.w = acc[ih * 4 + i][jh * 4 + 3] + bb.w;
                *(float4*)(C + (size_t)row * 1024 + col) = o;
            }
        }
    }
}

// ---------------------------------------------------------------------------
// Fused sparse attention: one block per (n, h, 16-query tile).
// Scores 16 x 2048 live in SMEM. Per-row exact radix select of the K_SEL-th
// largest score -> threshold; masked softmax; P @ V.
// ---------------------------------------------------------------------------
#define KV_CHUNK 256
#define ATTN_SMEM_FLOATS (16 * SCS + KV_CHUNK * 64 + 1024 + 2048 + 48)
#define ATTN_SMEM_BYTES  (ATTN_SMEM_FLOATS * 4)

__global__ __launch_bounds__(256, 1)
void attn_kernel()
{
    extern __shared__ float sm[];
    float*    sc     = sm;                          // [16][SCS] scores -> weights
    float*    kv     = sm + 16 * SCS;               // K: [64][256] e-major / V: [256][64] s-major
    float*    qt     = kv + KV_CHUNK * 64;          // Q^T [64][16] (later PV stage)
    unsigned* hist   = (unsigned*)(qt + 1024);      // 8 warps x 256 bins
    unsigned* s_tkey = hist + 2048;                 // [16]
    unsigned* s_umax = s_tkey + 16;                 // [16]
    float*    s_sum  = (float*)(s_umax + 16);       // [16]

    const int tid = threadIdx.x;
    const int n = blockIdx.z, h = blockIdx.y;
    const int l0 = blockIdx.x * 16;

    // ---- Load Q tile transposed, pre-scaled by 1/sqrt(D) ----
    {
        const int row = tid >> 4, e4 = tid & 15;
        const float4 q = *(const float4*)(g_Qp + (size_t)((l0 + row) * 2 + n) * 1024 + h * 64 + e4 * 4);
        qt[(e4 * 4 + 0) * 16 + row] = q.x * 0.125f;
        qt[(e4 * 4 + 1) * 16 + row] = q.y * 0.125f;
        qt[(e4 * 4 + 2) * 16 + row] = q.z * 0.125f;
        qt[(e4 * 4 + 3) * 16 + row] = q.w * 0.125f;
    }

    // ---- Phase 1: scores = Q K^T / sqrt(D); 4x4 micro-tile, 256-key chunks ----
    {
        const int rb = tid >> 6, cb = tid & 63;     // 4 row-quads x 64 col-quads
        for (int s0 = 0; s0 < S_DIM; s0 += KV_CHUNK) {
            // load K chunk transposed: kv[e][s_local], s_local in [0,256)
#pragma unroll
            for (int i = 0; i < 16; ++i) {
                const int idx = i * 256 + tid;
                const int sr = idx & 255, e4 = idx >> 8;
                const float4 k = *(const float4*)(g_Kp + (size_t)((s0 + sr) * 2 + n) * 1024 + h * 64 + e4 * 4);
                kv[(e4 * 4 + 0) * 256 + sr] = k.x;
                kv[(e4 * 4 + 1) * 256 + sr] = k.y;
                kv[(e4 * 4 + 2) * 256 + sr] = k.z;
                kv[(e4 * 4 + 3) * 256 + sr] = k.w;
            }
            __syncthreads();
            float acc[4][4];
#pragma unroll
            for (int r = 0; r < 4; ++r)
#pragma unroll
                for (int c = 0; c < 4; ++c) acc[r][c] = 0.0f;
            const float* qp = qt + rb * 4;
            const float* kp = kv + cb * 4;
#pragma unroll 16
            for (int e = 0; e < 64; ++e) {
                const float4 q4 = *(const float4*)(qp + e * 16);
                const float4 k4 = *(const float4*)(kp + e * 256);
                const float qv[4] = {q4.x, q4.y, q4.z, q4.w};
#pragma unroll
                for (int r = 0; r < 4; ++r) {
                    acc[r][0] = fmaf(qv[r], k4.x, acc[r][0]);
                    acc[r][1] = fmaf(qv[r], k4.y, acc[r][1]);
                    acc[r][2] = fmaf(qv[r], k4.z, acc[r][2]);
                    acc[r][3] = fmaf(qv[r], k4.w, acc[r][3]);
                }
            }
#pragma unroll
            for (int r = 0; r < 4; ++r)
                *(float4*)(sc + (rb * 4 + r) * SCS + s0 + cb * 4) =
                    make_float4(acc[r][0], acc[r][1], acc[r][2], acc[r][3]);
            __syncthreads();
        }
    }

    // ---- Phase 2: per-row exact radix select (warp per 2 rows),
    //      warp-aggregated histogram atomics (scores cluster in few exponent bins)
    {
        const int wid = tid >> 5, lane = tid & 31;
        unsigned* hw = hist + wid * 256;
        for (int rr = 0; rr < 2; ++rr) {
            const int row = wid * 2 + rr;
            const float* srow = sc + row * SCS;
            // row max
            unsigned km = 0;
#pragma unroll 8
            for (int j = 0; j < 64; ++j) {
                const unsigned k = f2key(srow[lane + 32 * j]);
                km = (k > km) ? k : km;
            }
#pragma unroll
            for (int o = 16; o > 0; o >>= 1) {
                const unsigned v = __shfl_xor_sync(0xffffffffu, km, o);
                km = (v > km) ? v : km;
            }
            // MSB-first byte radix select for ascending rank T_SEL
            unsigned prefix = 0;
            unsigned T = T_SEL;
#pragma unroll
            for (int b = 3; b >= 0; --b) {
                for (int i = lane; i < 256; i += 32) hw[i] = 0;
                __syncwarp();
                const unsigned himask = (b == 3) ? 0u : (0xFFFFFFFFu << ((b + 1) * 8));
                for (int j = 0; j < 64; ++j) {
                    const unsigned key = f2key(srow[lane + 32 * j]);
                    const bool act = ((key & himask) == prefix);
                    const unsigned bin = (key >> (b * 8)) & 255;
                    // aggregate identical bins within the warp: one atomic per group
                    const unsigned tag = act ? bin : (0x100u + (unsigned)lane);
                    const unsigned grp = __match_any_sync(0xffffffffu, tag);
                    if (act && lane == (__ffs(grp) - 1))
                        atomicAdd(&hw[bin], (unsigned)__popc(grp));
                }
                __syncwarp();
                unsigned c[8], lsum = 0;
#pragma unroll
                for (int i = 0; i < 8; ++i) { c[i] = hw[lane * 8 + i]; lsum += c[i]; }
                unsigned inc = lsum;
#pragma unroll
                for (int o = 1; o < 32; o <<= 1) {
                    const unsigned v = __shfl_up_sync(0xffffffffu, inc, o);
                    if (lane >= o) inc += v;
                }
                const unsigned exl = inc - lsum;
                const bool own = (T >= exl) && (T < exl + lsum);
                const unsigned bal = __ballot_sync(0xffffffffu, own);
                const int src = __ffs(bal) - 1;
                unsigned bsel = 0, nT = 0;
                if (own) {
                    unsigned cum = exl;
#pragma unroll
                    for (int i = 0; i < 8; ++i) {
                        if (T < cum + c[i]) { bsel = (unsigned)(lane * 8 + i); nT = T - cum; break; }
                        cum += c[i];
                    }
                }
                bsel = __shfl_sync(0xffffffffu, bsel, src);
                nT   = __shfl_sync(0xffffffffu, nT, src);
                prefix |= bsel << (b * 8);
                T = nT;
                __syncwarp();
            }
            if (lane == 0) { s_tkey[row] = prefix; s_umax[row] = km; s_sum[row] = 0.0f; }
        }
    }
    __syncthreads();

    // ---- Phase 3: masked exp weights + row sums (in place over sc) ----
    {
        const int row = tid >> 4;
        const unsigned tk = s_tkey[row];
        const float m = key2f(s_umax[row]);
        float lsum = 0.0f;
        float* srow = sc + row * SCS + (tid & 15);
#pragma unroll 4
        for (int j = 0; j < 128; ++j) {
            const float x = srow[j * 16];
            float w = 0.0f;
            if (f2key(x) >= tk) w = fexp(x - m);
            srow[j * 16] = w;
            lsum += w;
        }
        atomicAdd(&s_sum[row], lsum);
    }
    __syncthreads();

    // ---- Phase 4: O = W @ V (s split across two thread groups, 256-s chunks) ----
    const int g = tid >> 7, pos = tid & 127, prb = pos >> 4, pcb = pos & 15;
    float oa[4] = {0, 0, 0, 0}, ob[4] = {0, 0, 0, 0};
    for (int s0 = 0; s0 < S_DIM; s0 += KV_CHUNK) {
#pragma unroll
        for (int i = 0; i < 16; ++i) {
            const int idx = i * 256 + tid;
            const int sr = idx >> 4, d4 = idx & 15;
            const float4 v = *(const float4*)(g_Vp + (size_t)((s0 + sr) * 2 + n) * 1024 + h * 64 + d4 * 4);
            *(float4*)(kv + sr * 64 + d4 * 4) = v;
        }
        __syncthreads();
        const float* w0 = sc + (prb * 2) * SCS + s0 + g * 128;
        const float* w1 = w0 + SCS;
        const float* vp = kv + (g * 128) * 64 + pcb * 4;
#pragma unroll 8
        for (int sl = 0; sl < 128; ++sl) {
            const float wa = w0[sl], wb = w1[sl];
            const float4 v = *(const float4*)(vp + sl * 64);
            oa[0] = fmaf(wa, v.x, oa[0]);
            oa[1] = fmaf(wa, v.y, oa[1]);
            oa[2] = fmaf(wa, v.z, oa[2]);
            oa[3] = fmaf(wa, v.w, oa[3]);
            ob[0] = fmaf(wb, v.x, ob[0]);
            ob[1] = fmaf(wb, v.y, ob[1]);
            ob[2] = fmaf(wb, v.z, ob[2]);
            ob[3] = fmaf(wb, v.w, ob[3]);
        }
        __syncthreads();
    }

    // ---- Phase 5: cross-group reduce, normalize, scatter (d-major output) ----
    float* stage = qt;  // Q tile no longer needed
    if (g == 1) {
        *(float4*)(stage + pos * 8)     = make_float4(oa[0], oa[1], oa[2], oa[3]);
        *(float4*)(stage + pos * 8 + 4) = make_float4(ob[0], ob[1], ob[2], ob[3]);
    }
    __syncthreads();
    if (g == 0) {
        const float4 pa = *(const float4*)(stage + pos * 8);
        const float4 pb = *(const float4*)(stage + pos * 8 + 4);
        const float inv0 = 1.0f / s_sum[prb * 2];
        const float inv1 = 1.0f / s_sum[prb * 2 + 1];
        const int r0 = l0 + prb * 2;
        float* o0 = g_O + (size_t)(r0 * 2 + n) * 1024 + h;        // + d*16
        float* o1 = g_O + (size_t)((r0 + 1) * 2 + n) * 1024 + h;
        o0[(pcb * 4 + 0) * 16] = (oa[0] + pa.x) * inv0;
        o0[(pcb * 4 + 1) * 16] = (oa[1] + pa.y) * inv0;
        o0[(pcb * 4 + 2) * 16] = (oa[2] + pa.z) * inv0;
        o0[(pcb * 4 + 3) * 16] = (oa[3] + pa.w) * inv0;
        o1[(pcb * 4 + 0) * 16] = (ob[0] + pb.x) * inv1;
        o1[(pcb * 4 + 1) * 16] = (ob[1] + pb.y) * inv1;
        o1[(pcb * 4 + 2) * 16] = (ob[2] + pb.z) * inv1;
        o1[(pcb * 4 + 3) * 16] = (ob[3] + pb.w) * inv1;
    }
}

// ---------------------------------------------------------------------------
// Launch
// ---------------------------------------------------------------------------
extern "C" void kernel_launch(void* const* d_in, const int* in_sizes, int n_in,
                              void* d_out, int out_size)
{
    (void)in_sizes; (void)n_in; (void)out_size;
    const float* query = (const float*)d_in[0];
    const float* key   = (const float*)d_in[1];
    const float* value = (const float*)d_in[2];
    const float* Wq = (const float*)d_in[3];
    const float* bq = (const float*)d_in[4];
    const float* Wk = (const float*)d_in[5];
    const float* bk = (const float*)d_in[6];
    const float* Wv = (const float*)d_in[7];
    const float* bv = (const float*)d_in[8];
    const float* Wo = (const float*)d_in[9];
    const float* bo = (const float*)d_in[10];

    float *Qp, *Kp, *Vp, *O;
    cudaGetSymbolAddress((void**)&Qp, g_Qp);
    cudaGetSymbolAddress((void**)&Kp, g_Kp);
    cudaGetSymbolAddress((void**)&Vp, g_Vp);
    cudaGetSymbolAddress((void**)&O,  g_O);

    cudaFuncSetAttribute(attn_kernel, cudaFuncAttributeMaxDynamicSharedMemorySize,
                         ATTN_SMEM_BYTES);

    const dim3 gg(8, 32, 1);   // (N/128, M/128)
    gemm_bias_kernel<<<gg, 256>>>(query, Wq, bq, Qp);
    gemm_bias_kernel<<<gg, 256>>>(key,   Wk, bk, Kp);
    gemm_bias_kernel<<<gg, 256>>>(value, Wv, bv, Vp);

    attn_kernel<<<dim3(L_DIM / 16, H_N, N_B), 256, ATTN_SMEM_BYTES>>>();

    gemm_bias_kernel<<<gg, 256>>>(O, Wo, bo, (float*)d_out);
}

// round 5
// speedup vs baseline: 1.0005x; 1.0005x over previous
#include <cuda_runtime.h>
#include <cstdint>

// Problem constants
#define L_DIM   2048
#define N_B     2
#define E_DIM   1024
#define H_N     16
#define D_H     64
#define S_DIM   2048
#define K_SEL   1176              // int(2048 * sigmoid(0.3))
#define T_SEL   (S_DIM - K_SEL)   // 872: 0-based ascending rank of threshold
#define SCS     2052              // score row stride in smem floats (bank-skewed)

// Scratch (static device arrays are allowed; cudaMalloc is not)
__device__ float g_Qp[4096 * 1024];
__device__ float g_Kp[4096 * 1024];
__device__ float g_Vp[4096 * 1024];
__device__ float g_O [4096 * 1024];

// ---------------------------------------------------------------------------
// Helpers
// ---------------------------------------------------------------------------
__device__ __forceinline__ unsigned f2key(float f) {
    unsigned u = __float_as_uint(f);
    return (u & 0x80000000u) ? ~u : (u | 0x80000000u);
}
__device__ __forceinline__ float key2f(unsigned k) {
    unsigned u = (k & 0x80000000u) ? (k ^ 0x80000000u) : ~k;
    return __uint_as_float(u);
}
// Fast e^x for x <= 0 (poly exp2, ~1e-7 rel err). Avoids MUFU bottleneck.
__device__ __forceinline__ float fexp(float x) {
    float y = x * 1.4426950408889634f;
    y = fmaxf(y, -120.0f);
    float fl = floorf(y);
    float f  = y - fl;
    float p  =             1.53533619e-4f;
    p = fmaf(p, f, 1.33988744e-3f);
    p = fmaf(p, f, 9.61843736e-3f);
    p = fmaf(p, f, 5.55033247e-2f);
    p = fmaf(p, f, 2.40226479e-1f);
    p = fmaf(p, f, 6.93147203e-1f);
    p = fmaf(p, f, 1.0f);
    return p * __int_as_float(((int)fl + 127) << 23);
}

// ---------------------------------------------------------------------------
// GEMM: C[4096,1024] = A[4096,1024] @ B^T + bias,  B is [1024,1024] row-major
// (nn.Linear semantics: C[i,j] = sum_e A[i,e] * B[j,e] + bias[j])
// BM=BN=128, BK=16, 256 threads, 8x8 micro-tile, register prefetch of next tile.
// ---------------------------------------------------------------------------
__global__ __launch_bounds__(256, 2)
void gemm_bias_kernel(const float* __restrict__ A, const float* __restrict__ B,
                      const float* __restrict__ bias, float* __restrict__ C)
{
    __shared__ float As[16 * 128];
    __shared__ float Bs[16 * 128];
    const int tid = threadIdx.x;
    const int bm = blockIdx.y, bn = blockIdx.x;
    const int ty = tid >> 4, tx = tid & 15;
    const int rr = tid >> 2, k4 = tid & 3;   // loader coords (per-thread)

    float acc[8][8];
#pragma unroll
    for (int i = 0; i < 8; ++i)
#pragma unroll
        for (int j = 0; j < 8; ++j) acc[i][j] = 0.0f;

    const float* Abase = A + (size_t)(bm * 128 + rr) * 1024 + k4 * 4;
    const float* Bbase = B + (size_t)(bn * 128 + rr) * 1024 + k4 * 4;

    // prefetch regs: rows rr and rr+64 of the 128-row tile
    float4 pa0, pa1, pb0, pb1;
    pa0 = *(const float4*)(Abase);
    pa1 = *(const float4*)(Abase + (size_t)64 * 1024);
    pb0 = *(const float4*)(Bbase);
    pb1 = *(const float4*)(Bbase + (size_t)64 * 1024);

    for (int kt = 0; kt < 64; ++kt) {
        // store prefetched tile to smem (k-major, column = row-in-tile)
        As[(k4 * 4 + 0) * 128 + rr] = pa0.x;
        As[(k4 * 4 + 1) * 128 + rr] = pa0.y;
        As[(k4 * 4 + 2) * 128 + rr] = pa0.z;
        As[(k4 * 4 + 3) * 128 + rr] = pa0.w;
        As[(k4 * 4 + 0) * 128 + rr + 64] = pa1.x;
        As[(k4 * 4 + 1) * 128 + rr + 64] = pa1.y;
        As[(k4 * 4 + 2) * 128 + rr + 64] = pa1.z;
        As[(k4 * 4 + 3) * 128 + rr + 64] = pa1.w;
        Bs[(k4 * 4 + 0) * 128 + rr] = pb0.x;
        Bs[(k4 * 4 + 1) * 128 + rr] = pb0.y;
        Bs[(k4 * 4 + 2) * 128 + rr] = pb0.z;
        Bs[(k4 * 4 + 3) * 128 + rr] = pb0.w;
        Bs[(k4 * 4 + 0) * 128 + rr + 64] = pb1.x;
        Bs[(k4 * 4 + 1) * 128 + rr + 64] = pb1.y;
        Bs[(k4 * 4 + 2) * 128 + rr + 64] = pb1.z;
        Bs[(k4 * 4 + 3) * 128 + rr + 64] = pb1.w;
        __syncthreads();

        if (kt < 63) {    // issue next-tile loads; latency hidden by compute
            const int off = (kt + 1) * 16;
            pa0 = *(const float4*)(Abase + off);
            pa1 = *(const float4*)(Abase + (size_t)64 * 1024 + off);
            pb0 = *(const float4*)(Bbase + off);
            pb1 = *(const float4*)(Bbase + (size_t)64 * 1024 + off);
        }

#pragma unroll
        for (int k = 0; k < 16; ++k) {
            const float4 a0 = *(const float4*)(As + k * 128 + ty * 4);
            const float4 a1 = *(const float4*)(As + k * 128 + 64 + ty * 4);
            const float4 b0 = *(const float4*)(Bs + k * 128 + tx * 4);
            const float4 b1 = *(const float4*)(Bs + k * 128 + 64 + tx * 4);
            const float av[8] = {a0.x, a0.y, a0.z, a0.w, a1.x, a1.y, a1.z, a1.w};
            const float bv[8] = {b0.x, b0.y, b0.z, b0.w, b1.x, b1.y, b1.z, b1.w};
#pragma unroll
            for (int ii = 0; ii < 8; ++ii)
#pragma unroll
                for (int jj = 0; jj < 8; ++jj)
                    acc[ii][jj] = fmaf(av[ii], bv[jj], acc[ii][jj]);
        }
        __syncthreads();
    }
    // Epilogue with bias
#pragma unroll
    for (int jh = 0; jh < 2; ++jh) {
        const int col = bn * 128 + jh * 64 + tx * 4;
        const float4 bb = *(const float4*)(bias + col);
#pragma unroll
        for (int ih = 0; ih < 2; ++ih) {
#pragma unroll
            for (int i = 0; i < 4; ++i) {
                const int row = bm * 128 + ih * 64 + ty * 4 + i;
                float4 o;
                o.x = acc[ih * 4 + i][jh * 4 + 0] + bb.x;
                o.y = acc[ih * 4 + i][jh * 4 + 1] + bb.y;
                o.z = acc[ih * 4 + i][jh * 4 + 2] + bb.z;
                o.w = acc[ih * 4 + i][jh * 4 + 3] + bb.w;
                *(float4*)(C + (size_t)row * 1024 + col) = o;
            }
        }
    }
}

// ---------------------------------------------------------------------------
// Fused sparse attention: one block per (n, h, 16-query tile).
// Scores 16 x 2048 live in SMEM. Per-row exact radix select of the K_SEL-th
// largest score -> threshold; masked softmax; P @ V.
// ---------------------------------------------------------------------------
#define KV_CHUNK 256
#define ATTN_SMEM_FLOATS (16 * SCS + KV_CHUNK * 64 + 1024 + 2048 + 48)
#define ATTN_SMEM_BYTES  (ATTN_SMEM_FLOATS * 4)

__global__ __launch_bounds__(256, 1)
void attn_kernel()
{
    extern __shared__ float sm[];
    float*    sc     = sm;                          // [16][SCS] scores -> weights
    float*    kv     = sm + 16 * SCS;               // K: [64][256] e-major / V: [256][64] s-major
    float*    qt     = kv + KV_CHUNK * 64;          // Q^T [64][16] (later PV stage)
    unsigned* hist   = (unsigned*)(qt + 1024);      // 8 warps x 256 bins
    unsigned* s_tkey = hist + 2048;                 // [16]
    unsigned* s_umax = s_tkey + 16;                 // [16]
    float*    s_sum  = (float*)(s_umax + 16);       // [16]

    const int tid = threadIdx.x;
    const int n = blockIdx.z, h = blockIdx.y;
    const int l0 = blockIdx.x * 16;

    // ---- Load Q tile transposed, pre-scaled by 1/sqrt(D) ----
    {
        const int row = tid >> 4, e4 = tid & 15;
        const float4 q = *(const float4*)(g_Qp + (size_t)((l0 + row) * 2 + n) * 1024 + h * 64 + e4 * 4);
        qt[(e4 * 4 + 0) * 16 + row] = q.x * 0.125f;
        qt[(e4 * 4 + 1) * 16 + row] = q.y * 0.125f;
        qt[(e4 * 4 + 2) * 16 + row] = q.z * 0.125f;
        qt[(e4 * 4 + 3) * 16 + row] = q.w * 0.125f;
    }

    // ---- Phase 1: scores = Q K^T / sqrt(D); 4x4 micro-tile, 256-key chunks ----
    {
        const int rb = tid >> 6, cb = tid & 63;     // 4 row-quads x 64 col-quads
        for (int s0 = 0; s0 < S_DIM; s0 += KV_CHUNK) {
            // load K chunk transposed: kv[e][s_local], s_local in [0,256)
#pragma unroll
            for (int i = 0; i < 16; ++i) {
                const int idx = i * 256 + tid;
                const int sr = idx & 255, e4 = idx >> 8;
                const float4 k = *(const float4*)(g_Kp + (size_t)((s0 + sr) * 2 + n) * 1024 + h * 64 + e4 * 4);
                kv[(e4 * 4 + 0) * 256 + sr] = k.x;
                kv[(e4 * 4 + 1) * 256 + sr] = k.y;
                kv[(e4 * 4 + 2) * 256 + sr] = k.z;
                kv[(e4 * 4 + 3) * 256 + sr] = k.w;
            }
            __syncthreads();
            float acc[4][4];
#pragma unroll
            for (int r = 0; r < 4; ++r)
#pragma unroll
                for (int c = 0; c < 4; ++c) acc[r][c] = 0.0f;
            const float* qp = qt + rb * 4;
            const float* kp = kv + cb * 4;
#pragma unroll 16
            for (int e = 0; e < 64; ++e) {
                const float4 q4 = *(const float4*)(qp + e * 16);
                const float4 k4 = *(const float4*)(kp + e * 256);
                const float qv[4] = {q4.x, q4.y, q4.z, q4.w};
#pragma unroll
                for (int r = 0; r < 4; ++r) {
                    acc[r][0] = fmaf(qv[r], k4.x, acc[r][0]);
                    acc[r][1] = fmaf(qv[r], k4.y, acc[r][1]);
                    acc[r][2] = fmaf(qv[r], k4.z, acc[r][2]);
                    acc[r][3] = fmaf(qv[r], k4.w, acc[r][3]);
                }
            }
#pragma unroll
            for (int r = 0; r < 4; ++r)
                *(float4*)(sc + (rb * 4 + r) * SCS + s0 + cb * 4) =
                    make_float4(acc[r][0], acc[r][1], acc[r][2], acc[r][3]);
            __syncthreads();
        }
    }

    // ---- Phase 2: per-row exact radix select (warp per 2 rows),
    //      warp-aggregated histogram atomics (scores cluster in few exponent bins)
    {
        const int wid = tid >> 5, lane = tid & 31;
        unsigned* hw = hist + wid * 256;
        for (int rr = 0; rr < 2; ++rr) {
            const int row = wid * 2 + rr;
            const float* srow = sc + row * SCS;
            // row max
            unsigned km = 0;
#pragma unroll 8
            for (int j = 0; j < 64; ++j) {
                const unsigned k = f2key(srow[lane + 32 * j]);
                km = (k > km) ? k : km;
            }
#pragma unroll
            for (int o = 16; o > 0; o >>= 1) {
                const unsigned v = __shfl_xor_sync(0xffffffffu, km, o);
                km = (v > km) ? v : km;
            }
            // MSB-first byte radix select for ascending rank T_SEL
            unsigned prefix = 0;
            unsigned T = T_SEL;
#pragma unroll
            for (int b = 3; b >= 0; --b) {
                for (int i = lane; i < 256; i += 32) hw[i] = 0;
                __syncwarp();
                const unsigned himask = (b == 3) ? 0u : (0xFFFFFFFFu << ((b + 1) * 8));
                for (int j = 0; j < 64; ++j) {
                    const unsigned key = f2key(srow[lane + 32 * j]);
                    const bool act = ((key & himask) == prefix);
                    const unsigned bin = (key >> (b * 8)) & 255;
                    // aggregate identical bins within the warp: one atomic per group
                    const unsigned tag = act ? bin : (0x100u + (unsigned)lane);
                    const unsigned grp = __match_any_sync(0xffffffffu, tag);
                    if (act && lane == (__ffs(grp) - 1))
                        atomicAdd(&hw[bin], (unsigned)__popc(grp));
                }
                __syncwarp();
                unsigned c[8], lsum = 0;
#pragma unroll
                for (int i = 0; i < 8; ++i) { c[i] = hw[lane * 8 + i]; lsum += c[i]; }
                unsigned inc = lsum;
#pragma unroll
                for (int o = 1; o < 32; o <<= 1) {
                    const unsigned v = __shfl_up_sync(0xffffffffu, inc, o);
                    if (lane >= o) inc += v;
                }
                const unsigned exl = inc - lsum;
                const bool own = (T >= exl) && (T < exl + lsum);
                const unsigned bal = __ballot_sync(0xffffffffu, own);
                const int src = __ffs(bal) - 1;
                unsigned bsel = 0, nT = 0;
                if (own) {
                    unsigned cum = exl;
#pragma unroll
                    for (int i = 0; i < 8; ++i) {
                        if (T < cum + c[i]) { bsel = (unsigned)(lane * 8 + i); nT = T - cum; break; }
                        cum += c[i];
                    }
                }
                bsel = __shfl_sync(0xffffffffu, bsel, src);
                nT   = __shfl_sync(0xffffffffu, nT, src);
                prefix |= bsel << (b * 8);
                T = nT;
                __syncwarp();
            }
            if (lane == 0) { s_tkey[row] = prefix; s_umax[row] = km; s_sum[row] = 0.0f; }
        }
    }
    __syncthreads();

    // ---- Phase 3: masked exp weights + row sums (in place over sc) ----
    {
        const int row = tid >> 4;
        const unsigned tk = s_tkey[row];
        const float m = key2f(s_umax[row]);
        float lsum = 0.0f;
        float* srow = sc + row * SCS + (tid & 15);
#pragma unroll 4
        for (int j = 0; j < 128; ++j) {
            const float x = srow[j * 16];
            float w = 0.0f;
            if (f2key(x) >= tk) w = fexp(x - m);
            srow[j * 16] = w;
            lsum += w;
        }
        atomicAdd(&s_sum[row], lsum);
    }
    __syncthreads();

    // ---- Phase 4: O = W @ V (s split across two thread groups, 256-s chunks) ----
    const int g = tid >> 7, pos = tid & 127, prb = pos >> 4, pcb = pos & 15;
    float oa[4] = {0, 0, 0, 0}, ob[4] = {0, 0, 0, 0};
    for (int s0 = 0; s0 < S_DIM; s0 += KV_CHUNK) {
#pragma unroll
        for (int i = 0; i < 16; ++i) {
            const int idx = i * 256 + tid;
            const int sr = idx >> 4, d4 = idx & 15;
            const float4 v = *(const float4*)(g_Vp + (size_t)((s0 + sr) * 2 + n) * 1024 + h * 64 + d4 * 4);
            *(float4*)(kv + sr * 64 + d4 * 4) = v;
        }
        __syncthreads();
        const float* w0 = sc + (prb * 2) * SCS + s0 + g * 128;
        const float* w1 = w0 + SCS;
        const float* vp = kv + (g * 128) * 64 + pcb * 4;
#pragma unroll 8
        for (int sl = 0; sl < 128; ++sl) {
            const float wa = w0[sl], wb = w1[sl];
            const float4 v = *(const float4*)(vp + sl * 64);
            oa[0] = fmaf(wa, v.x, oa[0]);
            oa[1] = fmaf(wa, v.y, oa[1]);
            oa[2] = fmaf(wa, v.z, oa[2]);
            oa[3] = fmaf(wa, v.w, oa[3]);
            ob[0] = fmaf(wb, v.x, ob[0]);
            ob[1] = fmaf(wb, v.y, ob[1]);
            ob[2] = fmaf(wb, v.z, ob[2]);
            ob[3] = fmaf(wb, v.w, ob[3]);
        }
        __syncthreads();
    }

    // ---- Phase 5: cross-group reduce, normalize, scatter (d-major output) ----
    float* stage = qt;  // Q tile no longer needed
    if (g == 1) {
        *(float4*)(stage + pos * 8)     = make_float4(oa[0], oa[1], oa[2], oa[3]);
        *(float4*)(stage + pos * 8 + 4) = make_float4(ob[0], ob[1], ob[2], ob[3]);
    }
    __syncthreads();
    if (g == 0) {
        const float4 pa = *(const float4*)(stage + pos * 8);
        const float4 pb = *(const float4*)(stage + pos * 8 + 4);
        const float inv0 = 1.0f / s_sum[prb * 2];
        const float inv1 = 1.0f / s_sum[prb * 2 + 1];
        const int r0 = l0 + prb * 2;
        float* o0 = g_O + (size_t)(r0 * 2 + n) * 1024 + h;        // + d*16
        float* o1 = g_O + (size_t)((r0 + 1) * 2 + n) * 1024 + h;
        o0[(pcb * 4 + 0) * 16] = (oa[0] + pa.x) * inv0;
        o0[(pcb * 4 + 1) * 16] = (oa[1] + pa.y) * inv0;
        o0[(pcb * 4 + 2) * 16] = (oa[2] + pa.z) * inv0;
        o0[(pcb * 4 + 3) * 16] = (oa[3] + pa.w) * inv0;
        o1[(pcb * 4 + 0) * 16] = (ob[0] + pb.x) * inv1;
        o1[(pcb * 4 + 1) * 16] = (ob[1] + pb.y) * inv1;
        o1[(pcb * 4 + 2) * 16] = (ob[2] + pb.z) * inv1;
        o1[(pcb * 4 + 3) * 16] = (ob[3] + pb.w) * inv1;
    }
}

// ---------------------------------------------------------------------------
// Launch
// ---------------------------------------------------------------------------
extern "C" void kernel_launch(void* const* d_in, const int* in_sizes, int n_in,
                              void* d_out, int out_size)
{
    (void)in_sizes; (void)n_in; (void)out_size;
    const float* query = (const float*)d_in[0];
    const float* key   = (const float*)d_in[1];
    const float* value = (const float*)d_in[2];
    const float* Wq = (const float*)d_in[3];
    const float* bq = (const float*)d_in[4];
    const float* Wk = (const float*)d_in[5];
    const float* bk = (const float*)d_in[6];
    const float* Wv = (const float*)d_in[7];
    const float* bv = (const float*)d_in[8];
    const float* Wo = (const float*)d_in[9];
    const float* bo = (const float*)d_in[10];

    float *Qp, *Kp, *Vp, *O;
    cudaGetSymbolAddress((void**)&Qp, g_Qp);
    cudaGetSymbolAddress((void**)&Kp, g_Kp);
    cudaGetSymbolAddress((void**)&Vp, g_Vp);
    cudaGetSymbolAddress((void**)&O,  g_O);

    cudaFuncSetAttribute(attn_kernel, cudaFuncAttributeMaxDynamicSharedMemorySize,
                         ATTN_SMEM_BYTES);

    const dim3 gg(8, 32, 1);   // (N/128, M/128)
    gemm_bias_kernel<<<gg, 256>>>(query, Wq, bq, Qp);
    gemm_bias_kernel<<<gg, 256>>>(key,   Wk, bk, Kp);
    gemm_bias_kernel<<<gg, 256>>>(value, Wv, bv, Vp);

    attn_kernel<<<dim3(L_DIM / 16, H_N, N_B), 256, ATTN_SMEM_BYTES>>>();

    gemm_bias_kernel<<<gg, 256>>>(O, Wo, bo, (float*)d_out);
}